// round 10
// baseline (speedup 1.0000x reference)
#include <cuda_runtime.h>
#include <cuda_fp16.h>

#define HD   160
#define PLN  25600          // W*D
#define VOL  4096000        // H*W*D
#define NVOX 8192000ULL     // 2*160^3
#define WSEG 80             // passDW w-outputs per block
#define NR   90             // rows processed per passDW block (WSEG + 10)
#define PRE  4              // smem prefetch depth (rows)
#define RING 6              // smem row-ring slots
#define SEG  40             // passH slide segment
#define NSEG 4              // HD/SEG
#define NBBC 1280           // passH grid blocks: 4*160*2

// Normalized 1D Gaussian, KS=11, sigma=1.5
__device__ constexpr float GW[11] = {
    0.00102838f, 0.00759876f, 0.03600077f, 0.10936070f, 0.21300553f,
    0.26601172f,
    0.21300553f, 0.10936070f, 0.03600077f, 0.00759876f, 0.00102838f
};

constexpr float C1f  = 1.0e-4f;
constexpr float C2f  = 9.0e-4f;
constexpr float EPSf = 1.0e-12f;

// fp16 scratch: gC = D+W-blurred fields.
__device__ __half gC[5ULL * NVOX];
__device__ double g_acc;
__device__ unsigned int g_ticket;

__device__ __forceinline__ int refl(int i) {
    return (i < 0) ? -i : ((i > HD - 1) ? (2 * (HD - 1) - i) : i);
}

// ---------------------------------------------------------------------------
// passDW: fused D-blur (+5 field products) and W-blur.
// Block = (w-half 80, h, b), 160 threads (t = d).
// Barrier every 2 iterations (safe: reads {j,j+1}%6, writes {j+4,j+5}%6).
// Inner unroll of 22 keeps ring slots and barrier parity compile-time.
// ---------------------------------------------------------------------------
__global__ void __launch_bounds__(HD) passDW(const float* __restrict__ src,
                                             const float* __restrict__ ref) {
    __shared__ float S[RING][172];
    __shared__ float R[RING][172];

    const int t  = threadIdx.x;
    const int b  = blockIdx.z;
    const int h  = blockIdx.y;
    const int w0 = blockIdx.x * WSEG;

    const size_t bh = ((size_t)(b * HD + h)) * PLN;

    const bool loT = (t < 6);
    const bool hiT = (t >= 154);
    const int  hpos = loT ? t : (t + 12);            // halo smem position
    const int  hgl  = loT ? (6 - t) : (312 - t);     // halo global d

    // Prologue: rows 0..PRE-1 straight into smem.
    for (int m = 0; m < PRE; ++m) {
        const size_t base = bh + (size_t)refl(w0 - 5 + m) * HD;
        S[m][6 + t] = __ldg(src + base + t);
        R[m][6 + t] = __ldg(ref + base + t);
        if (loT || hiT) {
            S[m][hpos] = __ldg(src + base + hgl);
            R[m][hpos] = __ldg(ref + base + hgl);
        }
    }
    // Prefetch row PRE into registers.
    float sM, rM, sH = 0.f, rH = 0.f;
    {
        const size_t base = bh + (size_t)refl(w0 - 5 + PRE) * HD;
        sM = __ldg(src + base + t);
        rM = __ldg(ref + base + t);
        if (loT || hiT) { sH = __ldg(src + base + hgl); rH = __ldg(ref + base + hgl); }
    }

    // Register ring of D-blurred fields.
    float q0[11], q1[11], q2[11], q3[11], q4[11];

    int scur = 0;        // j % RING
    int spre = PRE;      // (j+PRE) % RING

    #pragma unroll 1
    for (int c = 0; c < 5; ++c) {                 // 5 x 22 >= NR
        #pragma unroll
        for (int u = 0; u < 22; ++u) {
            const int j = c * 22 + u;
            if (j >= NR) break;
            if ((u & 1) == 0) __syncthreads();    // barrier every 2 iters

            // Retire prefetched row j+PRE into smem, then prefetch j+PRE+1.
            if (j + PRE < NR) {
                S[spre][6 + t] = sM;
                R[spre][6 + t] = rM;
                if (loT || hiT) { S[spre][hpos] = sH; R[spre][hpos] = rH; }
                if (j + PRE + 1 < NR) {
                    const size_t base = bh + (size_t)refl(w0 - 5 + j + PRE + 1) * HD;
                    sM = __ldg(src + base + t);
                    rM = __ldg(ref + base + t);
                    if (loT || hiT) { sH = __ldg(src + base + hgl); rH = __ldg(ref + base + hgl); }
                }
            }

            // D-blur row j (slot scur) -> ring slot u % 11 (compile-time:
            // c*22 is a multiple of 11).
            float a0 = 0.f, a1 = 0.f, a2 = 0.f, a3 = 0.f, a4 = 0.f;
            #pragma unroll
            for (int k = 0; k < 11; ++k) {
                const float s = S[scur][t + 1 + k];
                const float v = R[scur][t + 1 + k];
                const float ss = s * s, vv = v * v, sv = s * v;
                a0 = fmaf(GW[k], s,  a0);
                a1 = fmaf(GW[k], v,  a1);
                a2 = fmaf(GW[k], ss, a2);
                a3 = fmaf(GW[k], vv, a3);
                a4 = fmaf(GW[k], sv, a4);
            }
            const int sl = u % 11;
            q0[sl] = a0; q1[sl] = a1; q2[sl] = a2; q3[sl] = a3; q4[sl] = a4;

            if (++scur == RING) scur = 0;
            if (++spre == RING) spre = 0;

            // W-blur output w = w0 + j - 10 from ring rows j-10..j.
            if (j >= 10) {
                float m0 = 0.f, m1 = 0.f, m2 = 0.f, m3 = 0.f, m4 = 0.f;
                #pragma unroll
                for (int k = 0; k < 11; ++k) {
                    const int s2 = (u % 11 + 1 + k) % 11;
                    m0 = fmaf(GW[k], q0[s2], m0);
                    m1 = fmaf(GW[k], q1[s2], m1);
                    m2 = fmaf(GW[k], q2[s2], m2);
                    m3 = fmaf(GW[k], q3[s2], m3);
                    m4 = fmaf(GW[k], q4[s2], m4);
                }
                const size_t off = bh + (size_t)(w0 + j - 10) * HD + t;
                gC[0ULL * NVOX + off] = __float2half_rn(m0);
                gC[1ULL * NVOX + off] = __float2half_rn(m1);
                gC[2ULL * NVOX + off] = __float2half_rn(m2);
                gC[3ULL * NVOX + off] = __float2half_rn(m3);
                gC[4ULL * NVOX + off] = __float2half_rn(m4);
            }
        }
    }
}

// ---------------------------------------------------------------------------
// passH: H-blur + SSIM + reduce, prefetch distance 1 (5 temps consumed next
// iteration; retired into slot u after its old plane is read at k=0).
// Block (h-seg 40, w, b), 160 threads.
// ---------------------------------------------------------------------------
__global__ void __launch_bounds__(HD) passH(float* __restrict__ out) {
    const int d  = threadIdx.x;
    const int b  = blockIdx.z;
    const int w  = blockIdx.y;
    const int h0 = blockIdx.x * SEG;

    const size_t bw = (size_t)b * VOL + (size_t)w * HD + d;

    float win[5][11];

    #pragma unroll
    for (int m = 0; m < 11; ++m) {               // planes h0-5 .. h0+5
        const size_t off = bw + (size_t)refl(h0 - 5 + m) * PLN;
        #pragma unroll
        for (int f = 0; f < 5; ++f)
            win[f][m] = __half2float(__ldg(gC + (size_t)f * NVOX + off));
    }

    float acc = 0.f;

    #pragma unroll 1
    for (int c = 0; c < SEG / 11 + 1; ++c) {
        const int jbase = c * 11;
        #pragma unroll
        for (int u = 0; u < 11; ++u) {
            const int j = jbase + u;
            if (j >= SEG) break;
            // Prefetch plane h0+j+6 (consumed next iteration).
            float t0, t1, t2, t3, t4;
            {
                const size_t off = bw + (size_t)refl(h0 + j + 6) * PLN;
                t0 = __half2float(__ldg(gC + 0ULL * NVOX + off));
                t1 = __half2float(__ldg(gC + 1ULL * NVOX + off));
                t2 = __half2float(__ldg(gC + 2ULL * NVOX + off));
                t3 = __half2float(__ldg(gC + 3ULL * NVOX + off));
                t4 = __half2float(__ldg(gC + 4ULL * NVOX + off));
            }
            float mu1 = 0.f, mu2 = 0.f, m11 = 0.f, m22 = 0.f, m12 = 0.f;
            #pragma unroll
            for (int k = 0; k < 11; ++k) {
                const int sl = (u + k) % 11;
                mu1 = fmaf(GW[k], win[0][sl], mu1);
                mu2 = fmaf(GW[k], win[1][sl], mu2);
                m11 = fmaf(GW[k], win[2][sl], m11);
                m22 = fmaf(GW[k], win[3][sl], m22);
                m12 = fmaf(GW[k], win[4][sl], m12);
            }
            const float a  = mu1 * mu1;
            const float bb = mu2 * mu2;
            const float cc = mu1 * mu2;
            const float s1 = m11 - a, s2 = m22 - bb, s12 = m12 - cc;
            const float num = (2.f * cc + C1f) * (2.f * s12 + C2f);
            const float den = (a + bb + C1f) * (s1 + s2 + C2f);
            acc += __fdividef(num, den + EPSf);
            // Retire prefetch into slot u (old plane j-5 consumed at k=0).
            win[0][u] = t0; win[1][u] = t1; win[2][u] = t2;
            win[3][u] = t3; win[4][u] = t4;
        }
    }

    // Reduce: 5 warps -> smem -> atomicAdd(double), ticket finalize.
    float v = acc;
    #pragma unroll
    for (int o = 16; o > 0; o >>= 1) v += __shfl_down_sync(0xffffffffu, v, o);
    __shared__ float ws[5];
    if ((threadIdx.x & 31) == 0) ws[threadIdx.x >> 5] = v;
    __syncthreads();
    if (threadIdx.x == 0) {
        const float s = ws[0] + ws[1] + ws[2] + ws[3] + ws[4];
        atomicAdd(&g_acc, (double)s);
        __threadfence();
        const unsigned done = atomicAdd(&g_ticket, 1u);
        if (done == NBBC - 1) {
            const double vv = atomicAdd(&g_acc, 0.0);
            out[0] = (float)(1.0 - vv / (double)NVOX);
            g_acc = 0.0;
            g_ticket = 0u;
            __threadfence();
        }
    }
}

extern "C" void kernel_launch(void* const* d_in, const int* in_sizes, int n_in,
                              void* d_out, int out_size) {
    const float* src = (const float*)d_in[0];
    const float* ref = (const float*)d_in[1];
    float* out = (float*)d_out;

    passDW<<<dim3(HD / WSEG, HD, 2), HD>>>(src, ref);
    passH<<<dim3(NSEG, HD, 2), HD>>>(out);
}

// round 11
// speedup vs baseline: 1.1995x; 1.1995x over previous
#include <cuda_runtime.h>
#include <cuda_fp16.h>

#define HD   160
#define PLN  25600          // W*D
#define VOL  4096000        // H*W*D
#define NVOX 8192000ULL     // 2*160^3
#define WSEG 80             // passDW w-outputs per block
#define NR   90             // rows processed per passDW block (WSEG + 10)
#define PRE  4              // smem prefetch depth (rows)
#define RING 6              // smem row-ring slots
#define SEG  80             // passH slide segment
#define NBBC 640            // passH grid blocks: 2*160*2

// Normalized 1D Gaussian, KS=11, sigma=1.5
__device__ constexpr float GW[11] = {
    0.00102838f, 0.00759876f, 0.03600077f, 0.10936070f, 0.21300553f,
    0.26601172f,
    0.21300553f, 0.10936070f, 0.03600077f, 0.00759876f, 0.00102838f
};

constexpr float C1f  = 1.0e-4f;
constexpr float C2f  = 9.0e-4f;
constexpr float EPSf = 1.0e-12f;

// fp16 scratch: gC = D+W-blurred fields.
__device__ __half gC[5ULL * NVOX];
__device__ double g_acc;
__device__ unsigned int g_ticket;

__device__ __forceinline__ int refl(int i) {
    return (i < 0) ? -i : ((i > HD - 1) ? (2 * (HD - 1) - i) : i);
}

// ---------------------------------------------------------------------------
// passDW: fused D-blur (+5 field products) and W-blur. (R9 form, measured
// as part of 157.3us best: ~98us.) Block = (w-half 80, h, b), 160 threads.
// ---------------------------------------------------------------------------
__global__ void __launch_bounds__(HD) passDW(const float* __restrict__ src,
                                             const float* __restrict__ ref) {
    __shared__ float S[RING][172];
    __shared__ float R[RING][172];

    const int t  = threadIdx.x;
    const int b  = blockIdx.z;
    const int h  = blockIdx.y;
    const int w0 = blockIdx.x * WSEG;

    const size_t bh = ((size_t)(b * HD + h)) * PLN;

    const bool loT = (t < 6);
    const bool hiT = (t >= 154);
    const int  hpos = loT ? t : (t + 12);            // halo smem position
    const int  hgl  = loT ? (6 - t) : (312 - t);     // halo global d

    // Prologue: rows 0..PRE-1 straight into smem.
    for (int m = 0; m < PRE; ++m) {
        const size_t base = bh + (size_t)refl(w0 - 5 + m) * HD;
        S[m][6 + t] = __ldg(src + base + t);
        R[m][6 + t] = __ldg(ref + base + t);
        if (loT || hiT) {
            S[m][hpos] = __ldg(src + base + hgl);
            R[m][hpos] = __ldg(ref + base + hgl);
        }
    }
    // Prefetch row PRE into registers.
    float sM, rM, sH = 0.f, rH = 0.f;
    {
        const size_t base = bh + (size_t)refl(w0 - 5 + PRE) * HD;
        sM = __ldg(src + base + t);
        rM = __ldg(ref + base + t);
        if (loT || hiT) { sH = __ldg(src + base + hgl); rH = __ldg(ref + base + hgl); }
    }

    // Register ring of D-blurred fields.
    float q0[11], q1[11], q2[11], q3[11], q4[11];

    int scur = 0;        // j % RING
    int spre = PRE;      // (j+PRE) % RING

    #pragma unroll 1
    for (int c = 0; c < 9; ++c) {
        #pragma unroll
        for (int u = 0; u < 11; ++u) {
            const int j = c * 11 + u;
            if (j >= NR) break;
            __syncthreads();

            // Retire prefetched row j+PRE into smem, then prefetch j+PRE+1.
            if (j + PRE < NR) {
                S[spre][6 + t] = sM;
                R[spre][6 + t] = rM;
                if (loT || hiT) { S[spre][hpos] = sH; R[spre][hpos] = rH; }
                if (j + PRE + 1 < NR) {
                    const size_t base = bh + (size_t)refl(w0 - 5 + j + PRE + 1) * HD;
                    sM = __ldg(src + base + t);
                    rM = __ldg(ref + base + t);
                    if (loT || hiT) { sH = __ldg(src + base + hgl); rH = __ldg(ref + base + hgl); }
                }
            }

            // D-blur row j (slot scur) -> ring slot u (== j % 11).
            float a0 = 0.f, a1 = 0.f, a2 = 0.f, a3 = 0.f, a4 = 0.f;
            #pragma unroll
            for (int k = 0; k < 11; ++k) {
                const float s = S[scur][t + 1 + k];
                const float v = R[scur][t + 1 + k];
                const float ss = s * s, vv = v * v, sv = s * v;
                a0 = fmaf(GW[k], s,  a0);
                a1 = fmaf(GW[k], v,  a1);
                a2 = fmaf(GW[k], ss, a2);
                a3 = fmaf(GW[k], vv, a3);
                a4 = fmaf(GW[k], sv, a4);
            }
            q0[u] = a0; q1[u] = a1; q2[u] = a2; q3[u] = a3; q4[u] = a4;

            if (++scur == RING) scur = 0;
            if (++spre == RING) spre = 0;

            // W-blur output w = w0 + j - 10 from ring rows j-10..j.
            if (j >= 10) {
                float m0 = 0.f, m1 = 0.f, m2 = 0.f, m3 = 0.f, m4 = 0.f;
                #pragma unroll
                for (int k = 0; k < 11; ++k) {
                    const int s2 = (u + 1 + k) % 11;
                    m0 = fmaf(GW[k], q0[s2], m0);
                    m1 = fmaf(GW[k], q1[s2], m1);
                    m2 = fmaf(GW[k], q2[s2], m2);
                    m3 = fmaf(GW[k], q3[s2], m3);
                    m4 = fmaf(GW[k], q4[s2], m4);
                }
                const size_t off = bh + (size_t)(w0 + j - 10) * HD + t;
                gC[0ULL * NVOX + off] = __float2half_rn(m0);
                gC[1ULL * NVOX + off] = __float2half_rn(m1);
                gC[2ULL * NVOX + off] = __float2half_rn(m2);
                gC[3ULL * NVOX + off] = __float2half_rn(m3);
                gC[4ULL * NVOX + off] = __float2half_rn(m4);
            }
        }
    }
}

// ---------------------------------------------------------------------------
// passH: H-blur + SSIM + reduce. 12-SLOT ring: iter j reads slots
// (j..j+10)%12 and loads plane j+6 into slot (j+11)%12, first consumed at
// k=10 of the NEXT iteration -> one full iteration of load-to-use distance
// with zero extra temps/moves. SEG=80: one balanced resident wave, less halo.
// Block (h-seg 80, w, b), 160 threads.
// ---------------------------------------------------------------------------
__global__ void __launch_bounds__(HD) passH(float* __restrict__ out) {
    const int d  = threadIdx.x;
    const int b  = blockIdx.z;
    const int w  = blockIdx.y;
    const int h0 = blockIdx.x * SEG;

    const size_t bw = (size_t)b * VOL + (size_t)w * HD + d;

    float win[5][12];

    // Warm-up: planes h0-5 .. h0+5 into slots 0..10.
    #pragma unroll
    for (int m = 0; m < 11; ++m) {
        const size_t off = bw + (size_t)refl(h0 - 5 + m) * PLN;
        #pragma unroll
        for (int f = 0; f < 5; ++f)
            win[f][m] = __half2float(__ldg(gC + (size_t)f * NVOX + off));
    }

    float acc = 0.f;

    #pragma unroll 1
    for (int c = 0; c < (SEG + 11) / 12; ++c) {
        const int jbase = c * 12;
        #pragma unroll
        for (int u = 0; u < 12; ++u) {
            const int j = jbase + u;
            if (j >= SEG) break;
            {   // load plane h0+j+6 into slot (u+11)%12 (read next iter, k=10)
                const size_t off = bw + (size_t)refl(h0 + j + 6) * PLN;
                #pragma unroll
                for (int f = 0; f < 5; ++f)
                    win[f][(u + 11) % 12] =
                        __half2float(__ldg(gC + (size_t)f * NVOX + off));
            }
            float mu1 = 0.f, mu2 = 0.f, m11 = 0.f, m22 = 0.f, m12 = 0.f;
            #pragma unroll
            for (int k = 0; k < 11; ++k) {
                const int sl = (u + k) % 12;
                mu1 = fmaf(GW[k], win[0][sl], mu1);
                mu2 = fmaf(GW[k], win[1][sl], mu2);
                m11 = fmaf(GW[k], win[2][sl], m11);
                m22 = fmaf(GW[k], win[3][sl], m22);
                m12 = fmaf(GW[k], win[4][sl], m12);
            }
            const float a  = mu1 * mu1;
            const float bb = mu2 * mu2;
            const float cc = mu1 * mu2;
            const float s1 = m11 - a, s2 = m22 - bb, s12 = m12 - cc;
            const float num = (2.f * cc + C1f) * (2.f * s12 + C2f);
            const float den = (a + bb + C1f) * (s1 + s2 + C2f);
            acc += __fdividef(num, den + EPSf);
        }
    }

    // Reduce: 5 warps -> smem -> atomicAdd(double), ticket finalize.
    float v = acc;
    #pragma unroll
    for (int o = 16; o > 0; o >>= 1) v += __shfl_down_sync(0xffffffffu, v, o);
    __shared__ float ws[5];
    if ((threadIdx.x & 31) == 0) ws[threadIdx.x >> 5] = v;
    __syncthreads();
    if (threadIdx.x == 0) {
        const float s = ws[0] + ws[1] + ws[2] + ws[3] + ws[4];
        atomicAdd(&g_acc, (double)s);
        __threadfence();
        const unsigned done = atomicAdd(&g_ticket, 1u);
        if (done == NBBC - 1) {
            const double vv = atomicAdd(&g_acc, 0.0);
            out[0] = (float)(1.0 - vv / (double)NVOX);
            g_acc = 0.0;
            g_ticket = 0u;
            __threadfence();
        }
    }
}

extern "C" void kernel_launch(void* const* d_in, const int* in_sizes, int n_in,
                              void* d_out, int out_size) {
    const float* src = (const float*)d_in[0];
    const float* ref = (const float*)d_in[1];
    float* out = (float*)d_out;

    passDW<<<dim3(HD / WSEG, HD, 2), HD>>>(src, ref);
    passH<<<dim3(HD / SEG, HD, 2), HD>>>(out);
}

// round 12
// speedup vs baseline: 1.2635x; 1.0533x over previous
#include <cuda_runtime.h>
#include <cuda_fp16.h>

#define HD   160
#define PLN  25600          // W*D
#define VOL  4096000        // H*W*D
#define NVOX 8192000ULL     // 2*160^3
#define WSEG 80             // passDW w-outputs per block
#define NR   90             // rows processed per passDW block (WSEG + 10)
#define PRE  4              // smem prefetch depth (rows)
#define RING 6              // smem row-ring slots
#define SEG  80             // passH slide segment
#define NBBC 640            // passH grid blocks: 2*160*2

// Normalized 1D Gaussian, KS=11, sigma=1.5
__device__ constexpr float GW[11] = {
    0.00102838f, 0.00759876f, 0.03600077f, 0.10936070f, 0.21300553f,
    0.26601172f,
    0.21300553f, 0.10936070f, 0.03600077f, 0.00759876f, 0.00102838f
};

constexpr float C1f  = 1.0e-4f;
constexpr float C2f  = 9.0e-4f;
constexpr float EPSf = 1.0e-12f;

// Interleaved fp16 scratch: one 16-byte record per voxel holding the 5
// D+W-blurred fields (f0..f4) + padding. One STG.128 write / LDG.128 read.
__device__ uint4 gI[NVOX];
__device__ double g_acc;
__device__ unsigned int g_ticket;

__device__ __forceinline__ int refl(int i) {
    return (i < 0) ? -i : ((i > HD - 1) ? (2 * (HD - 1) - i) : i);
}

// ---------------------------------------------------------------------------
// passDW: fused D-blur (+5 field products) and W-blur. (R9/R11 form;
// only the output store changed to one interleaved STG.128.)
// Block = (w-half 80, h, b), 160 threads (t = d).
// ---------------------------------------------------------------------------
__global__ void __launch_bounds__(HD) passDW(const float* __restrict__ src,
                                             const float* __restrict__ ref) {
    __shared__ float S[RING][172];
    __shared__ float R[RING][172];

    const int t  = threadIdx.x;
    const int b  = blockIdx.z;
    const int h  = blockIdx.y;
    const int w0 = blockIdx.x * WSEG;

    const size_t bh = ((size_t)(b * HD + h)) * PLN;

    const bool loT = (t < 6);
    const bool hiT = (t >= 154);
    const int  hpos = loT ? t : (t + 12);            // halo smem position
    const int  hgl  = loT ? (6 - t) : (312 - t);     // halo global d

    // Prologue: rows 0..PRE-1 straight into smem.
    for (int m = 0; m < PRE; ++m) {
        const size_t base = bh + (size_t)refl(w0 - 5 + m) * HD;
        S[m][6 + t] = __ldg(src + base + t);
        R[m][6 + t] = __ldg(ref + base + t);
        if (loT || hiT) {
            S[m][hpos] = __ldg(src + base + hgl);
            R[m][hpos] = __ldg(ref + base + hgl);
        }
    }
    // Prefetch row PRE into registers.
    float sM, rM, sH = 0.f, rH = 0.f;
    {
        const size_t base = bh + (size_t)refl(w0 - 5 + PRE) * HD;
        sM = __ldg(src + base + t);
        rM = __ldg(ref + base + t);
        if (loT || hiT) { sH = __ldg(src + base + hgl); rH = __ldg(ref + base + hgl); }
    }

    // Register ring of D-blurred fields.
    float q0[11], q1[11], q2[11], q3[11], q4[11];

    int scur = 0;        // j % RING
    int spre = PRE;      // (j+PRE) % RING

    #pragma unroll 1
    for (int c = 0; c < 9; ++c) {
        #pragma unroll
        for (int u = 0; u < 11; ++u) {
            const int j = c * 11 + u;
            if (j >= NR) break;
            __syncthreads();

            // Retire prefetched row j+PRE into smem, then prefetch j+PRE+1.
            if (j + PRE < NR) {
                S[spre][6 + t] = sM;
                R[spre][6 + t] = rM;
                if (loT || hiT) { S[spre][hpos] = sH; R[spre][hpos] = rH; }
                if (j + PRE + 1 < NR) {
                    const size_t base = bh + (size_t)refl(w0 - 5 + j + PRE + 1) * HD;
                    sM = __ldg(src + base + t);
                    rM = __ldg(ref + base + t);
                    if (loT || hiT) { sH = __ldg(src + base + hgl); rH = __ldg(ref + base + hgl); }
                }
            }

            // D-blur row j (slot scur) -> ring slot u (== j % 11).
            float a0 = 0.f, a1 = 0.f, a2 = 0.f, a3 = 0.f, a4 = 0.f;
            #pragma unroll
            for (int k = 0; k < 11; ++k) {
                const float s = S[scur][t + 1 + k];
                const float v = R[scur][t + 1 + k];
                const float ss = s * s, vv = v * v, sv = s * v;
                a0 = fmaf(GW[k], s,  a0);
                a1 = fmaf(GW[k], v,  a1);
                a2 = fmaf(GW[k], ss, a2);
                a3 = fmaf(GW[k], vv, a3);
                a4 = fmaf(GW[k], sv, a4);
            }
            q0[u] = a0; q1[u] = a1; q2[u] = a2; q3[u] = a3; q4[u] = a4;

            if (++scur == RING) scur = 0;
            if (++spre == RING) spre = 0;

            // W-blur output w = w0 + j - 10 from ring rows j-10..j.
            if (j >= 10) {
                float m0 = 0.f, m1 = 0.f, m2 = 0.f, m3 = 0.f, m4 = 0.f;
                #pragma unroll
                for (int k = 0; k < 11; ++k) {
                    const int s2 = (u + 1 + k) % 11;
                    m0 = fmaf(GW[k], q0[s2], m0);
                    m1 = fmaf(GW[k], q1[s2], m1);
                    m2 = fmaf(GW[k], q2[s2], m2);
                    m3 = fmaf(GW[k], q3[s2], m3);
                    m4 = fmaf(GW[k], q4[s2], m4);
                }
                uint4 rec;
                *reinterpret_cast<__half2*>(&rec.x) = __floats2half2_rn(m0, m1);
                *reinterpret_cast<__half2*>(&rec.y) = __floats2half2_rn(m2, m3);
                *reinterpret_cast<__half2*>(&rec.z) = __floats2half2_rn(m4, 0.f);
                rec.w = 0u;
                gI[bh + (size_t)(w0 + j - 10) * HD + t] = rec;
            }
        }
    }
}

// ---------------------------------------------------------------------------
// passH: H-blur + SSIM + reduce. 12-slot ring (R11 form); plane load is now
// ONE LDG.128 of the interleaved record + 3 half2->float2 unpacks.
// Block (h-seg 80, w, b), 160 threads.
// ---------------------------------------------------------------------------
__global__ void __launch_bounds__(HD) passH(float* __restrict__ out) {
    const int d  = threadIdx.x;
    const int b  = blockIdx.z;
    const int w  = blockIdx.y;
    const int h0 = blockIdx.x * SEG;

    const size_t bw = (size_t)b * VOL + (size_t)w * HD + d;

    float win[5][12];

    // Warm-up: planes h0-5 .. h0+5 into slots 0..10.
    #pragma unroll
    for (int m = 0; m < 11; ++m) {
        const uint4 v = __ldg(gI + bw + (size_t)refl(h0 - 5 + m) * PLN);
        const float2 f01 = __half22float2(*reinterpret_cast<const __half2*>(&v.x));
        const float2 f23 = __half22float2(*reinterpret_cast<const __half2*>(&v.y));
        const float2 f4  = __half22float2(*reinterpret_cast<const __half2*>(&v.z));
        win[0][m] = f01.x; win[1][m] = f01.y;
        win[2][m] = f23.x; win[3][m] = f23.y;
        win[4][m] = f4.x;
    }

    float acc = 0.f;

    #pragma unroll 1
    for (int c = 0; c < (SEG + 11) / 12; ++c) {
        const int jbase = c * 12;
        #pragma unroll
        for (int u = 0; u < 12; ++u) {
            const int j = jbase + u;
            if (j >= SEG) break;
            {   // load plane h0+j+6 into slot (u+11)%12 (read next iter, k=10)
                const uint4 v = __ldg(gI + bw + (size_t)refl(h0 + j + 6) * PLN);
                const float2 f01 = __half22float2(*reinterpret_cast<const __half2*>(&v.x));
                const float2 f23 = __half22float2(*reinterpret_cast<const __half2*>(&v.y));
                const float2 f4  = __half22float2(*reinterpret_cast<const __half2*>(&v.z));
                const int sl = (u + 11) % 12;
                win[0][sl] = f01.x; win[1][sl] = f01.y;
                win[2][sl] = f23.x; win[3][sl] = f23.y;
                win[4][sl] = f4.x;
            }
            float mu1 = 0.f, mu2 = 0.f, m11 = 0.f, m22 = 0.f, m12 = 0.f;
            #pragma unroll
            for (int k = 0; k < 11; ++k) {
                const int sl = (u + k) % 12;
                mu1 = fmaf(GW[k], win[0][sl], mu1);
                mu2 = fmaf(GW[k], win[1][sl], mu2);
                m11 = fmaf(GW[k], win[2][sl], m11);
                m22 = fmaf(GW[k], win[3][sl], m22);
                m12 = fmaf(GW[k], win[4][sl], m12);
            }
            const float a  = mu1 * mu1;
            const float bb = mu2 * mu2;
            const float cc = mu1 * mu2;
            const float s1 = m11 - a, s2 = m22 - bb, s12 = m12 - cc;
            const float num = (2.f * cc + C1f) * (2.f * s12 + C2f);
            const float den = (a + bb + C1f) * (s1 + s2 + C2f);
            acc += __fdividef(num, den + EPSf);
        }
    }

    // Reduce: 5 warps -> smem -> atomicAdd(double), ticket finalize.
    float v = acc;
    #pragma unroll
    for (int o = 16; o > 0; o >>= 1) v += __shfl_down_sync(0xffffffffu, v, o);
    __shared__ float ws[5];
    if ((threadIdx.x & 31) == 0) ws[threadIdx.x >> 5] = v;
    __syncthreads();
    if (threadIdx.x == 0) {
        const float s = ws[0] + ws[1] + ws[2] + ws[3] + ws[4];
        atomicAdd(&g_acc, (double)s);
        __threadfence();
        const unsigned done = atomicAdd(&g_ticket, 1u);
        if (done == NBBC - 1) {
            const double vv = atomicAdd(&g_acc, 0.0);
            out[0] = (float)(1.0 - vv / (double)NVOX);
            g_acc = 0.0;
            g_ticket = 0u;
            __threadfence();
        }
    }
}

extern "C" void kernel_launch(void* const* d_in, const int* in_sizes, int n_in,
                              void* d_out, int out_size) {
    const float* src = (const float*)d_in[0];
    const float* ref = (const float*)d_in[1];
    float* out = (float*)d_out;

    passDW<<<dim3(HD / WSEG, HD, 2), HD>>>(src, ref);
    passH<<<dim3(HD / SEG, HD, 2), HD>>>(out);
}